// round 2
// baseline (speedup 1.0000x reference)
#include <cuda_runtime.h>

// Problem constants
#define TSEQ 1024
#define NB   32      // batch
#define ID   512     // input dim
#define HD   512     // hidden dim
#define GD   2048    // 4*H gate rows
#define NBLK_DIR 64  // persistent blocks per direction (8 hidden units each)
#define REC_THREADS 256

// Scratch (device globals: no runtime allocation allowed)
__device__ float g_xw[(size_t)TSEQ * GD * NB];   // [t][g][b], bias (b_ih+b_hh) folded in. 256MB
__device__ float g_hbuf[2][2][HD * NB];          // [dir][pingpong][unit*32 + b]
__device__ unsigned g_barcnt[2];
__device__ unsigned g_bargen[2];

// ---------------------------------------------------------------------------
// Zero the output (it is poisoned; both directions atomicAdd into it)
// ---------------------------------------------------------------------------
__global__ void zero_out_kernel(float4* out, int n4) {
    int i = blockIdx.x * blockDim.x + threadIdx.x;
    if (i < n4) out[i] = make_float4(0.f, 0.f, 0.f, 0.f);
}

// ---------------------------------------------------------------------------
// xw[t][g][b] = sum_i x[t][b][i] * W_ih[g][i] + (b_ih[g] + b_hh[g])
// Block: one t, 64 gate rows, all 32 batch. 256 threads, thread = (warp g-octet, lane b).
// ---------------------------------------------------------------------------
__global__ __launch_bounds__(256) void xw_gemm(
    const float* __restrict__ x,
    const float* __restrict__ Wih,
    const float* __restrict__ bih,
    const float* __restrict__ bhh)
{
    __shared__ float xs[NB * 36];   // [b][kk], padded stride 36 (bank-safe, 16B aligned)
    __shared__ float ws[64 * 32];   // [g_local][kk]

    int t   = blockIdx.x >> 5;
    int g0  = (blockIdx.x & 31) << 6;
    int tid = threadIdx.x;
    int gg  = tid >> 5;   // warp id 0..7 (constant per warp -> uniform w loads)
    int b   = tid & 31;

    float acc[8];
#pragma unroll
    for (int j = 0; j < 8; j++) acc[j] = 0.f;

    const float* xt = x + (size_t)t * NB * ID;

    for (int k0 = 0; k0 < ID; k0 += 32) {
        // load x tile (32 b x 32 k), coalesced over k
#pragma unroll
        for (int r = 0; r < 4; r++) {
            int bl = (tid >> 5) + (r << 3);
            int kk = tid & 31;
            xs[bl * 36 + kk] = xt[bl * ID + k0 + kk];
        }
        // load W tile (64 g x 32 k), coalesced over k
#pragma unroll
        for (int r = 0; r < 8; r++) {
            int gl = (tid >> 5) + (r << 3);
            int kk = tid & 31;
            ws[gl * 32 + kk] = Wih[(size_t)(g0 + gl) * ID + k0 + kk];
        }
        __syncthreads();

#pragma unroll
        for (int kk = 0; kk < 32; kk += 4) {
            float4 xv = *(const float4*)&xs[b * 36 + kk];
#pragma unroll
            for (int j = 0; j < 8; j++) {
                float4 wv = *(const float4*)&ws[(gg * 8 + j) * 32 + kk];
                acc[j] += xv.x * wv.x;
                acc[j] += xv.y * wv.y;
                acc[j] += xv.z * wv.z;
                acc[j] += xv.w * wv.w;
            }
        }
        __syncthreads();
    }

    float* outp = g_xw + (size_t)t * GD * NB;
#pragma unroll
    for (int j = 0; j < 8; j++) {
        int g = g0 + gg * 8 + j;
        outp[g * NB + b] = acc[j] + bih[g] + bhh[g];
    }
}

// ---------------------------------------------------------------------------
// Persistent bidirectional zoneout-LSTM recurrence.
// 128 blocks resident: blocks 0..63 forward, 64..127 backward.
// Each block owns 8 hidden units (all 4 gates = 32 gate rows); c stays in SMEM.
// h is exchanged via L2 (ping-pong global buffers) + per-direction spin barrier.
// ---------------------------------------------------------------------------
__device__ __forceinline__ void dir_barrier(int dir, unsigned gen) {
    __syncthreads();
    if (threadIdx.x == 0) {
        __threadfence();  // make our h stores visible before arriving
        if (atomicAdd(&g_barcnt[dir], 1u) == (unsigned)(NBLK_DIR - 1)) {
            atomicExch(&g_barcnt[dir], 0u);
            __threadfence();
            atomicExch(&g_bargen[dir], gen + 1u);
        } else {
            while (*(volatile unsigned*)&g_bargen[dir] != gen + 1u) { }
            __threadfence();
        }
    }
    __syncthreads();
}

__global__ __launch_bounds__(REC_THREADS, 1) void lstm_rec(
    const float* __restrict__ Whh, float* __restrict__ out)
{
    extern __shared__ float smem[];
    // layout: ws4 (8 warps * 512 k * float4 = 64KB) | h_s (512*32 = 64KB) | gbuf (32*32) | c_s (8*32)
    float4* ws4 = (float4*)smem;
    float*  h_s = smem + 8 * 512 * 4;
    float*  gbuf = h_s + HD * NB;
    float*  c_s  = gbuf + 32 * 32;

    int bid  = blockIdx.x;
    int dir  = bid >> 6;
    int j0   = (bid & 63) << 3;   // first hidden unit of this block
    int tid  = threadIdx.x;
    int w    = tid >> 5;
    int lane = tid & 31;

    // gate rows owned by this warp: r = 4w+j -> global row (r>>3)*512 + j0 + (r&7)
    int grow[4];
#pragma unroll
    for (int j = 0; j < 4; j++) {
        int r = 4 * w + j;
        grow[j] = ((r >> 3) << 9) + j0 + (r & 7);
    }

    // Stage W_hh tile once: ws4[w][k] = (W[grow0][k], W[grow1][k], W[grow2][k], W[grow3][k])
    for (int it = 0; it < 16; it++) {
        int k = lane + (it << 5);
        float4 v;
        v.x = Whh[(size_t)grow[0] * HD + k];
        v.y = Whh[(size_t)grow[1] * HD + k];
        v.z = Whh[(size_t)grow[2] * HD + k];
        v.w = Whh[(size_t)grow[3] * HD + k];
        ws4[w * 512 + k] = v;
    }

    // init c = 0 (block-local), h buffer 0 = 0 (own units only)
    c_s[tid] = 0.f;
    {
        int u = tid >> 5;
        g_hbuf[dir][0][(j0 + u) * NB + lane] = 0.f;
    }

    unsigned gen = g_bargen[dir];   // current generation (fresh per launch: L1 flushed per launch)
    dir_barrier(dir, gen);          // ensure all blocks' h zero-init visible
    gen++;

    for (int s = 0; s < TSEQ; s++) {
        int t = dir ? (TSEQ - 1 - s) : s;
        const float* xw_t = g_xw + (size_t)t * GD * NB;

        // gate accumulators start at xw (+ folded biases) — long-latency DRAM loads issued early
        float acc0 = xw_t[grow[0] * NB + lane];
        float acc1 = xw_t[grow[1] * NB + lane];
        float acc2 = xw_t[grow[2] * NB + lane];
        float acc3 = xw_t[grow[3] * NB + lane];

        // load full h (all 512 units x 32 batch) from L2; .cg to bypass stale L1
        {
            const float4* hsrc = (const float4*)g_hbuf[dir][s & 1];
            float4* hdst = (float4*)h_s;
#pragma unroll
            for (int r = 0; r < 16; r++)
                hdst[tid + (r << 8)] = __ldcg(&hsrc[tid + (r << 8)]);
        }
        __syncthreads();

        // GEMV: 4 gate rows x 32 batch per warp over k=512
        const float4* wsw = ws4 + w * 512;
#pragma unroll 8
        for (int k = 0; k < HD; k++) {
            float h = h_s[(k << 5) + lane];
            float4 wv = wsw[k];
            acc0 += h * wv.x;
            acc1 += h * wv.y;
            acc2 += h * wv.z;
            acc3 += h * wv.w;
        }

        gbuf[(4 * w + 0) * 32 + lane] = acc0;
        gbuf[(4 * w + 1) * 32 + lane] = acc1;
        gbuf[(4 * w + 2) * 32 + lane] = acc2;
        gbuf[(4 * w + 3) * 32 + lane] = acc3;
        __syncthreads();

        // cell update: thread = (unit u, batch b); gbuf row = q*8+u for gate q (i,f,g,o)
        {
            int u = tid >> 5;
            int b = tid & 31;
            float iv = gbuf[(u) * 32 + b];
            float fv = gbuf[(8 + u) * 32 + b];
            float gv = gbuf[(16 + u) * 32 + b];
            float ov = gbuf[(24 + u) * 32 + b];
            iv = 1.f / (1.f + __expf(-iv));
            fv = 1.f / (1.f + __expf(-fv));
            gv = tanhf(gv);
            ov = 1.f / (1.f + __expf(-ov));
            float c_old = c_s[u * 32 + b];
            float h_old = h_s[(j0 + u) * 32 + b];
            float c_new = fv * c_old + iv * gv;
            float h_new = ov * tanhf(c_new);
            float c_bl = 0.9f * c_new + 0.1f * c_old;
            float h_bl = 0.9f * h_new + 0.1f * h_old;
            c_s[u * 32 + b] = c_bl;
            g_hbuf[dir][(s + 1) & 1][(j0 + u) * NB + b] = h_bl;
            // exactly two commutative fp32 adds per output element -> deterministic
            atomicAdd(&out[(size_t)t * (NB * HD) + b * HD + (j0 + u)], h_bl);
        }

        dir_barrier(dir, gen);
        gen++;
    }
}

// ---------------------------------------------------------------------------
extern "C" void kernel_launch(void* const* d_in, const int* in_sizes, int n_in,
                              void* d_out, int out_size) {
    const float* x   = (const float*)d_in[0];
    const float* Wih = (const float*)d_in[1];
    const float* Whh = (const float*)d_in[2];
    const float* bih = (const float*)d_in[3];
    const float* bhh = (const float*)d_in[4];
    float* out = (float*)d_out;

    const int rec_smem = (8 * 512 * 4 + HD * NB + 32 * 32 + 8 * 32) * (int)sizeof(float); // 136192 B
    cudaFuncSetAttribute(lstm_rec, cudaFuncAttributeMaxDynamicSharedMemorySize, rec_smem);

    int n4 = out_size / 4;
    zero_out_kernel<<<(n4 + 255) / 256, 256>>>((float4*)out, n4);
    xw_gemm<<<TSEQ * 32, 256>>>(x, Wih, bih, bhh);
    lstm_rec<<<2 * NBLK_DIR, REC_THREADS, rec_smem>>>(Whh, out);
}

// round 3
// speedup vs baseline: 1.1960x; 1.1960x over previous
#include <cuda_runtime.h>

// Problem constants
#define TSEQ 1024
#define NB   32      // batch
#define ID   512     // input dim
#define HD   512     // hidden dim
#define GD   2048    // 4*H gate rows
#define NBLK_DIR 64  // persistent blocks per direction (8 hidden units each)
#define REC_THREADS 256

typedef unsigned long long ull;

// Scratch (device globals: no runtime allocation allowed)
__device__ float g_xw[(size_t)TSEQ * GD * NB];   // [t][g][b], 256MB
// h in k-paired layout: g_hbuf[dir][ping][kp*64 + b*2 + (u&1)] where kp = u>>1
__device__ float g_hbuf[2][2][HD * NB];
__device__ unsigned g_barcnt[2];   // monotonic arrival counters (never reset)
__device__ unsigned g_bargen[2];   // monotonic generation

// ---------------------------------------------------------------------------
// packed fp32x2 FMA (Blackwell): d.xy += a.xy * b.xy
// ---------------------------------------------------------------------------
__device__ __forceinline__ void ffma2(ull& d, ull a, ull b) {
    asm("fma.rn.f32x2 %0, %1, %2, %0;" : "+l"(d) : "l"(a), "l"(b));
}
__device__ __forceinline__ float pairsum(ull v) {
    float2 f = *reinterpret_cast<float2*>(&v);
    return f.x + f.y;
}

__device__ __forceinline__ unsigned atom_add_acqrel(unsigned* p, unsigned v) {
    unsigned old;
    asm volatile("atom.acq_rel.gpu.add.u32 %0, [%1], %2;"
                 : "=r"(old) : "l"(p), "r"(v) : "memory");
    return old;
}
__device__ __forceinline__ unsigned ld_acquire(const unsigned* p) {
    unsigned v;
    asm volatile("ld.acquire.gpu.u32 %0, [%1];" : "=r"(v) : "l"(p) : "memory");
    return v;
}
__device__ __forceinline__ void st_release(unsigned* p, unsigned v) {
    asm volatile("st.release.gpu.u32 [%0], %1;" :: "l"(p), "r"(v) : "memory");
}

__device__ __forceinline__ float sigf(float x) {
    return __fdividef(1.f, 1.f + __expf(-x));
}
__device__ __forceinline__ float tanhfast(float x) {
    return __fdividef(2.f, 1.f + __expf(-2.f * x)) - 1.f;
}

// ---------------------------------------------------------------------------
// xw[t][g][b] = sum_i x[t][b][i] * W_ih[g][i] + (b_ih[g] + b_hh[g])
// Also zeroes its 2KB slice of d_out (atomicAdd target for the recurrence).
// ---------------------------------------------------------------------------
__global__ __launch_bounds__(256) void xw_gemm(
    const float* __restrict__ x,
    const float* __restrict__ Wih,
    const float* __restrict__ bih,
    const float* __restrict__ bhh,
    float4* __restrict__ out4)
{
    __shared__ float xs[NB * 36];   // [b][kk], padded stride 36
    __shared__ float ws[64 * 32];   // [g_local][kk]

    // fold output zeroing into this kernel (out poisoned; rec atomicAdds)
    if (threadIdx.x < 128)
        out4[(size_t)blockIdx.x * 128 + threadIdx.x] = make_float4(0.f, 0.f, 0.f, 0.f);

    int t   = blockIdx.x >> 5;
    int g0  = (blockIdx.x & 31) << 6;
    int tid = threadIdx.x;
    int gg  = tid >> 5;
    int b   = tid & 31;

    ull acc[8];
#pragma unroll
    for (int j = 0; j < 8; j++) acc[j] = 0ull;

    const float* xt = x + (size_t)t * NB * ID;

    for (int k0 = 0; k0 < ID; k0 += 32) {
#pragma unroll
        for (int r = 0; r < 4; r++) {
            int bl = (tid >> 5) + (r << 3);
            int kk = tid & 31;
            xs[bl * 36 + kk] = xt[bl * ID + k0 + kk];
        }
#pragma unroll
        for (int r = 0; r < 8; r++) {
            int gl = (tid >> 5) + (r << 3);
            int kk = tid & 31;
            ws[gl * 32 + kk] = Wih[(size_t)(g0 + gl) * ID + k0 + kk];
        }
        __syncthreads();

#pragma unroll
        for (int kk = 0; kk < 32; kk += 4) {
            ulonglong2 xv = *(const ulonglong2*)&xs[b * 36 + kk];
#pragma unroll
            for (int j = 0; j < 8; j++) {
                ulonglong2 wv = *(const ulonglong2*)&ws[(gg * 8 + j) * 32 + kk];
                ffma2(acc[j], xv.x, wv.x);
                ffma2(acc[j], xv.y, wv.y);
            }
        }
        __syncthreads();
    }

    float* outp = g_xw + (size_t)t * GD * NB;
#pragma unroll
    for (int j = 0; j < 8; j++) {
        int g = g0 + gg * 8 + j;
        outp[g * NB + b] = pairsum(acc[j]) + bih[g] + bhh[g];
    }
}

// ---------------------------------------------------------------------------
// Global spin barrier, per direction, monotonic (no reset, graph-replay safe)
// ---------------------------------------------------------------------------
__device__ __forceinline__ void dir_barrier(int dir, unsigned gen) {
    __syncthreads();
    if (threadIdx.x == 0) {
        unsigned old = atom_add_acqrel(&g_barcnt[dir], 1u);
        if (old == gen * (unsigned)NBLK_DIR + (NBLK_DIR - 1)) {
            st_release(&g_bargen[dir], gen + 1u);
        } else {
            while ((int)(ld_acquire(&g_bargen[dir]) - (gen + 1u)) < 0) { }
        }
    }
    __syncthreads();
}

// ---------------------------------------------------------------------------
// Persistent bidirectional zoneout-LSTM recurrence (f32x2 k-pair GEMV).
// 128 blocks: 0..63 fwd, 64..127 bwd. Block owns 8 hidden units (32 gate rows).
// Warp layout: w = rg + 4*kh; rg in 0..3 = gate, kh = k-half. Each warp: 8 rows
// (gate rg, units j0..j0+7) x 32 batches over 128 k-pairs.
// ---------------------------------------------------------------------------
__global__ __launch_bounds__(REC_THREADS, 1) void lstm_rec(
    const float* __restrict__ Whh, float* __restrict__ out)
{
    extern __shared__ float smem[];
    float4* wp4 = (float4*)smem;          // 4096 float4 = 64KB: [rg][kp][m] rows(2m,2m+1) k-pairs
    float*  hp  = smem + 16384;           // 64KB: hp[kp][b][2]  (k-paired h)
    float*  gbuf = hp + 16384;            // 8KB:  [w][j][b]
    float*  c_s  = gbuf + 2048;           // 1KB

    int bid  = blockIdx.x;
    int dir  = bid >> 6;
    int j0   = (bid & 63) << 3;
    int tid  = threadIdx.x;
    int w    = tid >> 5;
    int lane = tid & 31;
    int rg   = w & 3;
    int kh   = w >> 2;
    int u_l  = tid >> 5;          // cell-phase: unit-local 0..7
    int gu   = j0 + u_l;          // global unit for cell phase

    // Stage W_hh as k-pair float4s: wp4[(rg*256+kp)*4+m] =
    //   (W[rowA][2kp], W[rowA][2kp+1], W[rowA+1][2kp], W[rowA+1][2kp+1]),
    //   rowA = rg*512 + j0 + 2m
#pragma unroll
    for (int i = 0; i < 16; i++) {
        int idx = tid + (i << 8);
        int m   = idx & 3;
        int kp  = (idx >> 2) & 255;
        int rgi = idx >> 10;
        int rowA = (rgi << 9) + j0 + (m << 1);
        float2 a  = *(const float2*)&Whh[(size_t)rowA * HD + (kp << 1)];
        float2 bb = *(const float2*)&Whh[(size_t)(rowA + 1) * HD + (kp << 1)];
        wp4[idx] = make_float4(a.x, a.y, bb.x, bb.y);
    }

    // init c, and h(step 0) = 0 in global k-paired layout (own units only)
    c_s[tid] = 0.f;
    {
        int hidx = ((gu) >> 1) * 64 + (lane << 1) + (gu & 1);
        g_hbuf[dir][0][hidx] = 0.f;
    }

    unsigned gen = ld_acquire(&g_bargen[dir]);  // monotonic start (graph-replay safe)
    dir_barrier(dir, gen);
    gen++;

    const ull* hp_u = (const ull*)hp;

    for (int s = 0; s < TSEQ; s++) {
        int t = dir ? (TSEQ - 1 - s) : s;
        const float* xw_t = g_xw + (size_t)t * GD * NB;

        // prefetch xw for the cell phase (DRAM latency hidden under GEMV)
        float xg0 = xw_t[(0 * HD + gu) * NB + lane];
        float xg1 = xw_t[(1 * HD + gu) * NB + lane];
        float xg2 = xw_t[(2 * HD + gu) * NB + lane];
        float xg3 = xw_t[(3 * HD + gu) * NB + lane];

        // stage h (already k-paired in global): straight 64KB copy into smem
        {
            const float4* hsrc = (const float4*)g_hbuf[dir][s & 1];
            float4* hdst = (float4*)hp;
#pragma unroll
            for (int r = 0; r < 16; r++)
                hdst[tid + (r << 8)] = __ldcg(&hsrc[tid + (r << 8)]);
        }
        __syncthreads();

        // GEMV: 8 rows x 32 b per warp, 128 k-pairs, f32x2
        ull acc[8];
#pragma unroll
        for (int j = 0; j < 8; j++) acc[j] = 0ull;

        const ulonglong2* wb = (const ulonglong2*)(wp4 + (((rg << 8) + (kh << 7)) << 2));
        const ull* hb = hp_u + (kh << 12) + lane;

#pragma unroll 8
        for (int kp = 0; kp < 128; kp++) {
            ull h2 = hb[kp << 5];
            const ulonglong2* wk = wb + (kp << 2);
            ulonglong2 w01 = wk[0];
            ulonglong2 w23 = wk[1];
            ulonglong2 w45 = wk[2];
            ulonglong2 w67 = wk[3];
            ffma2(acc[0], h2, w01.x);
            ffma2(acc[1], h2, w01.y);
            ffma2(acc[2], h2, w23.x);
            ffma2(acc[3], h2, w23.y);
            ffma2(acc[4], h2, w45.x);
            ffma2(acc[5], h2, w45.y);
            ffma2(acc[6], h2, w67.x);
            ffma2(acc[7], h2, w67.y);
        }

        float* gb = gbuf + (w << 8);
#pragma unroll
        for (int j = 0; j < 8; j++)
            gb[(j << 5) + lane] = pairsum(acc[j]);
        __syncthreads();

        // cell update: thread = (unit u_l, batch lane); gate q partials in warps q, q+4
        {
            int b = lane;
            int uo = (u_l << 5) + b;
            float iv = xg0 + gbuf[0 * 256 + uo] + gbuf[4 * 256 + uo];
            float fv = xg1 + gbuf[1 * 256 + uo] + gbuf[5 * 256 + uo];
            float gv = xg2 + gbuf[2 * 256 + uo] + gbuf[6 * 256 + uo];
            float ov = xg3 + gbuf[3 * 256 + uo] + gbuf[7 * 256 + uo];
            iv = sigf(iv);
            fv = sigf(fv);
            gv = tanhfast(gv);
            ov = sigf(ov);
            int hidx = (gu >> 1) * 64 + (b << 1) + (gu & 1);
            float c_old = c_s[tid];
            float h_old = hp[hidx];
            float c_new = fv * c_old + iv * gv;
            float h_new = ov * tanhfast(c_new);
            float c_bl = 0.9f * c_new + 0.1f * c_old;
            float h_bl = 0.9f * h_new + 0.1f * h_old;
            c_s[tid] = c_bl;
            g_hbuf[dir][(s + 1) & 1][hidx] = h_bl;
            // exactly two commutative fp32 adds per output element -> deterministic
            atomicAdd(&out[(size_t)t * (NB * HD) + b * HD + gu], h_bl);
        }

        dir_barrier(dir, gen);
        gen++;
    }
}

// ---------------------------------------------------------------------------
extern "C" void kernel_launch(void* const* d_in, const int* in_sizes, int n_in,
                              void* d_out, int out_size) {
    const float* x   = (const float*)d_in[0];
    const float* Wih = (const float*)d_in[1];
    const float* Whh = (const float*)d_in[2];
    const float* bih = (const float*)d_in[3];
    const float* bhh = (const float*)d_in[4];
    float* out = (float*)d_out;

    const int rec_smem = (16384 + 16384 + 2048 + 256) * (int)sizeof(float); // 140288 B
    cudaFuncSetAttribute(lstm_rec, cudaFuncAttributeMaxDynamicSharedMemorySize, rec_smem);

    xw_gemm<<<TSEQ * 32, 256>>>(x, Wih, bih, bhh, (float4*)out);
    lstm_rec<<<2 * NBLK_DIR, REC_THREADS, rec_smem>>>(Whh, out);
}

// round 5
// speedup vs baseline: 1.3926x; 1.1644x over previous
#include <cuda_runtime.h>

// Problem constants
#define TSEQ 1024
#define NB   32      // batch
#define ID   512     // input dim
#define HD   512     // hidden dim
#define GD   2048    // 4*H gate rows
#define NBLK_DIR 64  // persistent blocks per direction (8 hidden units each)
#define REC_THREADS 256

typedef unsigned long long ull;

// Scratch (device globals: no runtime allocation allowed)
__device__ float g_xw[(size_t)TSEQ * GD * NB];   // [t][g][b], 256MB
// h in k-paired layout: g_hbuf[dir][ping][kp*64 + b*2 + (u&1)], kp = u>>1
__device__ float g_hbuf[2][2][HD * NB];
__device__ unsigned g_barcnt[2];   // monotonic arrival counters (never reset)
__device__ unsigned g_bargen[2];   // monotonic generation

// ---------------------------------------------------------------------------
// packed fp32x2 FMA (Blackwell): d.xy += a.xy * b.xy
// ---------------------------------------------------------------------------
__device__ __forceinline__ void ffma2(ull& d, ull a, ull b) {
    asm("fma.rn.f32x2 %0, %1, %2, %0;" : "+l"(d) : "l"(a), "l"(b));
}
__device__ __forceinline__ float pairsum(ull v) {
    float2 f = *reinterpret_cast<float2*>(&v);
    return f.x + f.y;
}

__device__ __forceinline__ unsigned atom_add_acqrel(unsigned* p, unsigned v) {
    unsigned old;
    asm volatile("atom.acq_rel.gpu.add.u32 %0, [%1], %2;"
                 : "=r"(old) : "l"(p), "r"(v) : "memory");
    return old;
}
__device__ __forceinline__ unsigned ld_acquire(const unsigned* p) {
    unsigned v;
    asm volatile("ld.acquire.gpu.u32 %0, [%1];" : "=r"(v) : "l"(p) : "memory");
    return v;
}
__device__ __forceinline__ void st_release(unsigned* p, unsigned v) {
    asm volatile("st.release.gpu.u32 [%0], %1;" :: "l"(p), "r"(v) : "memory");
}

__device__ __forceinline__ float sigf(float x) {
    return __fdividef(1.f, 1.f + __expf(-x));
}
__device__ __forceinline__ float tanhfast(float x) {
    return __fdividef(2.f, 1.f + __expf(-2.f * x)) - 1.f;
}

// ---------------------------------------------------------------------------
// xw[t][g][b] = sum_i x[t][b][i] * W_ih[g][i] + (b_ih[g] + b_hh[g])
// Also zeroes its 2KB slice of d_out.
// ---------------------------------------------------------------------------
__global__ __launch_bounds__(256) void xw_gemm(
    const float* __restrict__ x,
    const float* __restrict__ Wih,
    const float* __restrict__ bih,
    const float* __restrict__ bhh,
    float4* __restrict__ out4)
{
    __shared__ float xs[NB * 36];
    __shared__ float ws[64 * 32];

    if (threadIdx.x < 128)
        out4[(size_t)blockIdx.x * 128 + threadIdx.x] = make_float4(0.f, 0.f, 0.f, 0.f);

    int t   = blockIdx.x >> 5;
    int g0  = (blockIdx.x & 31) << 6;
    int tid = threadIdx.x;
    int gg  = tid >> 5;
    int b   = tid & 31;

    ull acc[8];
#pragma unroll
    for (int j = 0; j < 8; j++) acc[j] = 0ull;

    const float* xt = x + (size_t)t * NB * ID;

    for (int k0 = 0; k0 < ID; k0 += 32) {
#pragma unroll
        for (int r = 0; r < 4; r++) {
            int bl = (tid >> 5) + (r << 3);
            int kk = tid & 31;
            xs[bl * 36 + kk] = xt[bl * ID + k0 + kk];
        }
#pragma unroll
        for (int r = 0; r < 8; r++) {
            int gl = (tid >> 5) + (r << 3);
            int kk = tid & 31;
            ws[gl * 32 + kk] = Wih[(size_t)(g0 + gl) * ID + k0 + kk];
        }
        __syncthreads();

#pragma unroll
        for (int kk = 0; kk < 32; kk += 4) {
            ulonglong2 xv = *(const ulonglong2*)&xs[b * 36 + kk];
#pragma unroll
            for (int j = 0; j < 8; j++) {
                ulonglong2 wv = *(const ulonglong2*)&ws[(gg * 8 + j) * 32 + kk];
                ffma2(acc[j], xv.x, wv.x);
                ffma2(acc[j], xv.y, wv.y);
            }
        }
        __syncthreads();
    }

    float* outp = g_xw + (size_t)t * GD * NB;
#pragma unroll
    for (int j = 0; j < 8; j++) {
        int g = g0 + gg * 8 + j;
        outp[g * NB + b] = pairsum(acc[j]) + bih[g] + bhh[g];
    }
}

// ---------------------------------------------------------------------------
// Global spin barrier, per direction, monotonic (graph-replay safe)
// ---------------------------------------------------------------------------
__device__ __forceinline__ void dir_barrier(int dir, unsigned gen) {
    __syncthreads();
    if (threadIdx.x == 0) {
        unsigned old = atom_add_acqrel(&g_barcnt[dir], 1u);
        if (old == gen * (unsigned)NBLK_DIR + (NBLK_DIR - 1)) {
            st_release(&g_bargen[dir], gen + 1u);
        } else {
            while ((int)(ld_acquire(&g_bargen[dir]) - (gen + 1u)) < 0) { }
        }
    }
    __syncthreads();
}

// ---------------------------------------------------------------------------
// Persistent bidirectional zoneout-LSTM recurrence.
// 128 blocks: 0..63 fwd, 64..127 bwd. Block owns 8 hidden units (32 gate rows).
// Register-tile GEMV: warp w = (k-slice s4 = w>>1, batch-half wh = w&1);
// lane = (rg = lane&7 -> rows 4rg..4rg+3, bgl = lane>>3 -> batches wh*16+bgl*4..+3).
// Each lane: 4x4 outer-product tile over its 64 k-pairs, all LDS lane-distinct.
// Each warp stages EXACTLY the h float4 set it will read (race fix vs R4).
// ---------------------------------------------------------------------------
__global__ __launch_bounds__(REC_THREADS, 1) void lstm_rec(
    const float* __restrict__ Whh, float* __restrict__ out)
{
    extern __shared__ float smem[];
    float4* wsm  = (float4*)smem;         // 4096 float4 = 64KB: [(kp*2+j)*8 + rg]
    float*  hp   = smem + 16384;          // 64KB: hp[kp*64 + b*2 + kk]
    float*  gbuf = hp + 16384;            // 16KB: [s4][row][b]
    float*  c_s  = gbuf + 4096;           // 1KB

    int bid  = blockIdx.x;
    int dir  = bid >> 6;
    int j0   = (bid & 63) << 3;
    int tid  = threadIdx.x;
    int w    = tid >> 5;
    int lane = tid & 31;
    int s4   = w >> 1;          // k-slice 0..3 (64 kp each)
    int wh   = w & 1;           // batch half
    int rg   = lane & 7;        // row group (rows 4rg..4rg+3)
    int bgl  = lane >> 3;       // batch group within half
    int u_l  = tid >> 5;        // cell phase: unit-local 0..7
    int gu   = j0 + u_l;

    // Stage W_hh: wsm[(kp*2+j)*8 + rg] = (W[rA][2kp], W[rA][2kp+1], W[rB][2kp], W[rB][2kp+1])
    //   rA = 4rg+2j, rB = rA+1, global row(r) = (r>>3)*512 + j0 + (r&7)
#pragma unroll
    for (int i = 0; i < 16; i++) {
        int idx = tid + (i << 8);
        int rgi = idx & 7;
        int jj  = (idx >> 3) & 1;
        int kp  = idx >> 4;
        int rA  = 4 * rgi + 2 * jj;
        int rB  = rA + 1;
        int gA  = ((rA >> 3) << 9) + j0 + (rA & 7);
        int gB  = ((rB >> 3) << 9) + j0 + (rB & 7);
        float2 a  = *(const float2*)&Whh[(size_t)gA * HD + (kp << 1)];
        float2 bb = *(const float2*)&Whh[(size_t)gB * HD + (kp << 1)];
        wsm[idx] = make_float4(a.x, a.y, bb.x, bb.y);
    }

    // init c, h(step 0) = 0 in global k-paired layout (own units only)
    c_s[tid] = 0.f;
    {
        int hidx = (gu >> 1) * 64 + (lane << 1) + (gu & 1);
        g_hbuf[dir][0][hidx] = 0.f;
    }

    unsigned gen = ld_acquire(&g_bargen[dir]);
    dir_barrier(dir, gen);
    gen++;

    const ull* hp_u = (const ull*)hp;
    const ulonglong2* wq = (const ulonglong2*)wsm;
    const int kp0 = s4 << 6;
    const int hb_off = (wh << 4) + (bgl << 2);        // ull offset within a kp row

    for (int s = 0; s < TSEQ; s++) {
        int t = dir ? (TSEQ - 1 - s) : s;
        const float* xw_t = g_xw + (size_t)t * GD * NB;

        // prefetch xw for the cell phase (hidden under GEMV)
        float xg0 = xw_t[(0 * HD + gu) * NB + lane];
        float xg1 = xw_t[(1 * HD + gu) * NB + lane];
        float xg2 = xw_t[(2 * HD + gu) * NB + lane];
        float xg3 = xw_t[(3 * HD + gu) * NB + lane];

        // per-warp copy of EXACTLY the h float4 set this warp's GEMV reads:
        //   { (kp0 + l/8)*16 + wh*8 + (l&7)  :  l in [0,512) }
        // (4x128B chunks per load instruction -> fully coalesced)
        {
            const float4* hsrc = (const float4*)g_hbuf[dir][s & 1];
            float4* hdst = (float4*)hp;
#pragma unroll
            for (int i = 0; i < 16; i++) {
                int l = (i << 5) + lane;
                int idx = ((kp0 + (l >> 3)) << 4) + (wh << 3) + (l & 7);
                hdst[idx] = __ldcg(&hsrc[idx]);
            }
            __syncwarp();   // order cross-lane STS -> LDS within this warp
        }

        // GEMV: 4x4 register tile per lane over 64 k-pairs
        ull acc[4][4];
#pragma unroll
        for (int i = 0; i < 4; i++)
#pragma unroll
            for (int j = 0; j < 4; j++) acc[i][j] = 0ull;

#pragma unroll 4
        for (int kp = kp0; kp < kp0 + 64; kp++) {
            ulonglong2 h01 = *(const ulonglong2*)&hp_u[(kp << 5) + hb_off];
            ulonglong2 h23 = *(const ulonglong2*)&hp_u[(kp << 5) + hb_off + 2];
            ulonglong2 w01 = wq[((kp << 1) << 3) + rg];        // rows 4rg, 4rg+1
            ulonglong2 w23 = wq[(((kp << 1) + 1) << 3) + rg];  // rows 4rg+2, 4rg+3
            ffma2(acc[0][0], w01.x, h01.x);
            ffma2(acc[1][0], w01.y, h01.x);
            ffma2(acc[2][0], w23.x, h01.x);
            ffma2(acc[3][0], w23.y, h01.x);
            ffma2(acc[0][1], w01.x, h01.y);
            ffma2(acc[1][1], w01.y, h01.y);
            ffma2(acc[2][1], w23.x, h01.y);
            ffma2(acc[3][1], w23.y, h01.y);
            ffma2(acc[0][2], w01.x, h23.x);
            ffma2(acc[1][2], w01.y, h23.x);
            ffma2(acc[2][2], w23.x, h23.x);
            ffma2(acc[3][2], w23.y, h23.x);
            ffma2(acc[0][3], w01.x, h23.y);
            ffma2(acc[1][3], w01.y, h23.y);
            ffma2(acc[2][3], w23.x, h23.y);
            ffma2(acc[3][3], w23.y, h23.y);
        }

        // write partials: gbuf[s4][row][b], float4 over 4 consecutive batches
        {
            float4* gb4 = (float4*)gbuf;
#pragma unroll
            for (int i = 0; i < 4; i++) {
                int row = 4 * rg + i;
                gb4[((s4 << 5) + row) * 8 + (wh << 2) + bgl] =
                    make_float4(pairsum(acc[i][0]), pairsum(acc[i][1]),
                                pairsum(acc[i][2]), pairsum(acc[i][3]));
            }
        }
        __syncthreads();

        // cell update: thread = (unit u_l, batch lane); 4 k-slice partials per gate
        {
            int b = lane;
            float iv = xg0, fv = xg1, gv = xg2, ov = xg3;
#pragma unroll
            for (int q4 = 0; q4 < 4; q4++) {
                iv += gbuf[(((q4 << 5) + 0  + u_l) << 5) + b];
                fv += gbuf[(((q4 << 5) + 8  + u_l) << 5) + b];
                gv += gbuf[(((q4 << 5) + 16 + u_l) << 5) + b];
                ov += gbuf[(((q4 << 5) + 24 + u_l) << 5) + b];
            }
            iv = sigf(iv);
            fv = sigf(fv);
            gv = tanhfast(gv);
            ov = sigf(ov);
            int hidx = (gu >> 1) * 64 + (b << 1) + (gu & 1);
            float c_old = c_s[tid];
            float h_old = hp[hidx];
            float c_new = fv * c_old + iv * gv;
            float h_new = ov * tanhfast(c_new);
            float c_bl = 0.9f * c_new + 0.1f * c_old;
            float h_bl = 0.9f * h_new + 0.1f * h_old;
            c_s[tid] = c_bl;
            g_hbuf[dir][(s + 1) & 1][hidx] = h_bl;
            atomicAdd(&out[(size_t)t * (NB * HD) + b * HD + gu], h_bl);
        }

        dir_barrier(dir, gen);
        gen++;
    }
}

// ---------------------------------------------------------------------------
extern "C" void kernel_launch(void* const* d_in, const int* in_sizes, int n_in,
                              void* d_out, int out_size) {
    const float* x   = (const float*)d_in[0];
    const float* Wih = (const float*)d_in[1];
    const float* Whh = (const float*)d_in[2];
    const float* bih = (const float*)d_in[3];
    const float* bhh = (const float*)d_in[4];
    float* out = (float*)d_out;

    const int rec_smem = (16384 + 16384 + 4096 + 256) * (int)sizeof(float); // 148480 B
    cudaFuncSetAttribute(lstm_rec, cudaFuncAttributeMaxDynamicSharedMemorySize, rec_smem);

    xw_gemm<<<TSEQ * 32, 256>>>(x, Wih, bih, bhh, (float4*)out);
    lstm_rec<<<2 * NBLK_DIR, REC_THREADS, rec_smem>>>(Whh, out);
}